// round 2
// baseline (speedup 1.0000x reference)
#include <cuda_runtime.h>
#include <cstdint>

#define TT 1024
#define BB 128
#define CC 256
#define SS 128
#define LL 257          // 2*S+1
#define DEPTH 16        // cp.async row ring (power of 2)
#define NTHR 288        // 9 warps, one state per thread (257 active)
#define LOG2E 1.4426950408889634f
#define LN2F  0.6931471805599453f
#define NEG2  (-1.0e9f) // very negative in log2 units (finite; keeps arithmetic NaN-free)

__device__ float g_loss[BB];

__device__ __forceinline__ float fexp2(float x){ float y; asm("ex2.approx.ftz.f32 %0, %1;" : "=f"(y) : "f"(x)); return y; }
__device__ __forceinline__ float flog2(float x){ float y; asm("lg2.approx.f32 %0, %1;" : "=f"(y) : "f"(x)); return y; }

__device__ __forceinline__ void cp16(unsigned dst, const float* src){
  asm volatile("cp.async.cg.shared.global [%0], [%1], 16;" :: "r"(dst), "l"(src));
}
__device__ __forceinline__ void cp_commit(){ asm volatile("cp.async.commit_group;"); }
template<int N> __device__ __forceinline__ void cp_wait(){ asm volatile("cp.async.wait_group %0;" :: "n"(N)); }

__global__ void __launch_bounds__(NTHR, 1) ctc_fwd(
    const float* __restrict__ lp, const int* __restrict__ y,
    const int* __restrict__ ilen, const int* __restrict__ tlen)
{
  __shared__ __align__(16) float rowbuf[DEPTH][CC];   // 16 KB prefetch ring of log-prob rows
  __shared__ float alph[2][LL + 4];                   // double-buffered alpha (log2 units), 2-slot pad in front

  const int b   = blockIdx.x;
  const int tid = threadIdx.x;
  const int s   = tid;                                // extended-label state index
  const int len = ilen[b];
  const int tl  = tlen[b];

  // Per-thread class + skip-transition flag (precomputed once).
  int cls = 0; bool skipok = false;
  if (s < LL && (s & 1)) {
    int k = s >> 1;                                   // (s-1)/2 for odd s
    cls = y[b * SS + k];
    if (s >= 3) skipok = (cls != y[b * SS + k - 1]);
  }

  if (tid == 0) { alph[0][0]=NEG2; alph[0][1]=NEG2; alph[1][0]=NEG2; alph[1][1]=NEG2; }

  const unsigned rb_base = (unsigned)__cvta_generic_to_shared(&rowbuf[0][0]);
  const float* src0 = lp + (size_t)b * CC + (size_t)tid * 4;   // threads 0..63 load 16B each

  // Prologue: prefetch rows 0..DEPTH-1 (one commit group per row).
  #pragma unroll
  for (int r = 0; r < DEPTH; ++r) {
    if (tid < 64) cp16(rb_base + (unsigned)(r * (CC*4) + tid * 16), src0 + (size_t)r * (BB*CC));
    cp_commit();
  }
  cp_wait<DEPTH-2>();       // rows 0,1 complete
  __syncthreads();

  // Init alpha at t=0 (log2 domain): only s=0,1 reachable.
  float a = NEG2;
  if (s < LL) {
    if (s < 2) a = rowbuf[0][cls] * LOG2E;
    alph[0][s + 2] = a;
  }
  __syncthreads();

  #pragma unroll 1
  for (int t = 1; t < len; ++t) {
    // Prefetch row t+DEPTH-1 into slot (t-1)&15 (consumed last iteration).
    int pr = t + DEPTH - 1;
    if (tid < 64 && pr < len)
      cp16(rb_base + (unsigned)(((pr & (DEPTH-1)) * (CC*4)) + tid * 16),
           src0 + (size_t)pr * (BB*CC));
    cp_commit();

    if (s < LL) {
      float lpv  = rowbuf[t & (DEPTH-1)][cls];
      float emit = lpv * LOG2E;
      const float* old = alph[(t & 1) ^ 1];
      float a1 = old[s + 1];                          // alpha[s-1]
      float a2 = skipok ? old[s] : NEG2;              // alpha[s-2] if allowed
      float m  = fmaxf(a, fmaxf(a1, a2));
      float sum = fexp2(a - m) + fexp2(a1 - m) + fexp2(a2 - m);
      float anew = m + flog2(sum) + emit;
      a = anew;
      alph[t & 1][s + 2] = anew;
    }

    cp_wait<DEPTH-2>();   // row t+1 complete (issuing threads), published by the barrier
    __syncthreads();
  }

  if (tid == 0) {
    const float* fin = alph[(len - 1) & 1];
    float ahi = fin[2 * tl + 2];                       // state 2*tl
    float alo = fin[2 * tl + 1];                       // state 2*tl-1
    float m = fmaxf(ahi, alo);
    float ll2 = m + flog2(fexp2(ahi - m) + fexp2(alo - m));   // log2-likelihood
    float loss = -ll2 * LN2F;                          // nats
    if (!(loss < 0.5e9f)) loss = 0.f;                  // zero_infinity (also catches inf/nan)
    g_loss[b] = loss / (float)tl;
  }
}

__global__ void ctc_reduce(float* __restrict__ out)
{
  int tid = threadIdx.x;       // 128 threads
  float v = g_loss[tid];
  #pragma unroll
  for (int o = 16; o > 0; o >>= 1) v += __shfl_down_sync(0xffffffffu, v, o);
  __shared__ float part[4];
  if ((tid & 31) == 0) part[tid >> 5] = v;
  __syncthreads();
  if (tid == 0) out[0] = (part[0] + part[1] + part[2] + part[3]) * (1.0f / (float)BB);
}

extern "C" void kernel_launch(void* const* d_in, const int* in_sizes, int n_in,
                              void* d_out, int out_size)
{
  const float* lp  = (const float*)d_in[0];
  const int*   y   = (const int*)  d_in[1];
  const int*   il  = (const int*)  d_in[2];
  const int*   tl  = (const int*)  d_in[3];
  ctc_fwd<<<BB, NTHR>>>(lp, y, il, tl);
  ctc_reduce<<<1, 128>>>((float*)d_out);
}